// round 17
// baseline (speedup 1.0000x reference)
#include <cuda_runtime.h>
#include <cuda_bf16.h>
#include <cstdint>

// Problem constants (fixed shapes for this problem instance)
#define NN 50000
#define EE 800000
#define FF 128
#define HH 256
#define GG 512
#define TT 4

// ---------------- scratch (device globals: no allocation allowed) ----------
__device__ __align__(16) float g_dinv[NN];
__device__ __align__(16) float g_buf1[(size_t)NN * HH];   // GEMM outputs
__device__ __align__(16) float g_buf2[(size_t)NN * HH];   // agg / activations
__device__ __align__(16) float g_sums[GG * HH];
__device__ float g_cnt[GG];

// ---------------- degree / normalization ----------------------------------
__global__ void k_init_dinv() {
    int n = blockIdx.x * blockDim.x + threadIdx.x;
    if (n < NN) g_dinv[n] = 1.0f;   // self-loop contributes 1 to degree
}

__global__ void k_deg(const int* __restrict__ ei) {
    int e = blockIdx.x * blockDim.x + threadIdx.x;
    if (e < EE) atomicAdd(&g_dinv[ei[EE + e]], 1.0f);   // dst row
}

__global__ void k_fin_dinv() {
    int n = blockIdx.x * blockDim.x + threadIdx.x;
    if (n < NN) g_dinv[n] = rsqrtf(g_dinv[n]);          // deg >= 1 always
}

// ---------------- zero kernels ---------------------------------------------
__global__ void k_zero_buf2() {
    int i = blockIdx.x * blockDim.x + threadIdx.x;
    int stride = gridDim.x * blockDim.x;
    float4* p = (float4*)g_buf2;
    const int n4 = (NN * HH) / 4;
    for (int j = i; j < n4; j += stride) p[j] = make_float4(0.f, 0.f, 0.f, 0.f);
}

__global__ void k_zero_pool() {
    int i = blockIdx.x * blockDim.x + threadIdx.x;
    if (i < GG * HH) g_sums[i] = 0.0f;
    if (i < GG) g_cnt[i] = 0.0f;
}

// ---------------- SGEMM: C[M,256] = A[M,K] @ B[K,256] ----------------------
// 128x128 tile, BK=16, 256 threads, 8x8 microtile, 2-stage cp.async pipeline.
// A stored untransposed [m][16] (cp.async-friendly); compute reads A as
// scalar LDS.32 (2 addrs/warp, <=2 phases). B keeps the R15 conflict-free
// tx*4 / 64+tx*4 column mapping.
template<int K, bool SRC_BUF2>
__global__ void __launch_bounds__(256, 2) k_gemm(const float* __restrict__ Aarg,
                                                 const float* __restrict__ B) {
    const float* __restrict__ A = SRC_BUF2 ? (const float*)g_buf2 : Aarg;
    float* __restrict__ C = g_buf1;

    __shared__ __align__(16) float As[2][128 * 16];   // [m][k0..k0+16)
    __shared__ __align__(16) float Bs[2][16 * 128];   // [k][n]

    const int tid = threadIdx.x;
    const int tx = tid & 15;        // 16 col-groups
    const int ty = tid >> 4;        // 16 row-groups of 8
    const int m0 = blockIdx.y * 128;
    const int n0 = blockIdx.x * 128;

    float acc[8][8];
#pragma unroll
    for (int i = 0; i < 8; i++)
#pragma unroll
        for (int j = 0; j < 8; j++) acc[i][j] = 0.0f;

    // async loader: each thread copies 2x16B of A and 2x16B of B per stage
    auto load_stage = [&](int sbuf, int k0) {
        unsigned int abase = (unsigned int)__cvta_generic_to_shared(&As[sbuf][0]);
        unsigned int bbase = (unsigned int)__cvta_generic_to_shared(&Bs[sbuf][0]);
#pragma unroll
        for (int j = 0; j < 2; j++) {
            int cid = tid * 2 + j;          // 0..511
            int r = cid >> 2;               // 0..127 (A row)
            int sg = cid & 3;               // 16B segment within row
            bool valid = (m0 + r) < NN;
            const float* src = A + (valid ? ((size_t)(m0 + r) * K + k0 + sg * 4) : 0);
            int sz = valid ? 16 : 0;
            asm volatile("cp.async.cg.shared.global [%0], [%1], 16, %2;"
                         :: "r"(abase + (unsigned int)(r * 16 + sg * 4) * 4u),
                            "l"(src), "r"(sz));
        }
#pragma unroll
        for (int j = 0; j < 2; j++) {
            int cid = tid * 2 + j;          // 0..511
            int r = cid >> 5;               // 0..15 (B row)
            int sg = cid & 31;              // 16B segment (4 floats)
            const float* src = B + (size_t)(k0 + r) * HH + n0 + sg * 4;
            asm volatile("cp.async.cg.shared.global [%0], [%1], 16;"
                         :: "r"(bbase + (unsigned int)(r * 128 + sg * 4) * 4u),
                            "l"(src));
        }
    };

    load_stage(0, 0);
    asm volatile("cp.async.commit_group;");

    const int NIT = K / 16;
    for (int kt = 0; kt < NIT; kt++) {
        if (kt + 1 < NIT) load_stage((kt + 1) & 1, (kt + 1) * 16);
        asm volatile("cp.async.commit_group;");
        asm volatile("cp.async.wait_group 1;");
        __syncthreads();                    // stage kt data visible to all

        const float* __restrict__ Ab = &As[kt & 1][0];
        const float* __restrict__ Bb = &Bs[kt & 1][0];
#pragma unroll
        for (int k = 0; k < 16; k++) {
            float ar[8];
#pragma unroll
            for (int i = 0; i < 8; i++) ar[i] = Ab[(ty * 8 + i) * 16 + k];
            float4 b0 = *(const float4*)&Bb[k * 128 + tx * 4];        // cols tx*4
            float4 b1 = *(const float4*)&Bb[k * 128 + 64 + tx * 4];   // cols 64+tx*4
            float br[8] = { b0.x, b0.y, b0.z, b0.w, b1.x, b1.y, b1.z, b1.w };
#pragma unroll
            for (int i = 0; i < 8; i++)
#pragma unroll
                for (int j = 0; j < 8; j++)
                    acc[i][j] += ar[i] * br[j];
        }
        __syncthreads();                    // compute done before next overwrite
    }

#pragma unroll
    for (int i = 0; i < 8; i++) {
        int m = m0 + ty * 8 + i;
        if (m < NN) {
            float4 v0 = make_float4(acc[i][0], acc[i][1], acc[i][2], acc[i][3]);
            float4 v1 = make_float4(acc[i][4], acc[i][5], acc[i][6], acc[i][7]);
            *(float4*)(C + (size_t)m * HH + n0 + tx * 4)      = v0;   // cols tx*4
            *(float4*)(C + (size_t)m * HH + n0 + 64 + tx * 4) = v1;   // cols 64+tx*4
        }
    }
}

// ---------------- edge aggregation: agg[dst] += h[src] * norm --------------
// One warp per edge; float4 vector atomics (sm_90+) keep us on the LTS byte cap.
__global__ void k_agg(const int* __restrict__ ei) {
    int w = (blockIdx.x * blockDim.x + threadIdx.x) >> 5;
    int lane = threadIdx.x & 31;
    if (w >= EE) return;
    int s = ei[w];
    int d = ei[EE + w];
    float nrm = g_dinv[s] * g_dinv[d];
    const float4* __restrict__ hs = (const float4*)(g_buf1 + (size_t)s * HH);
    float4* __restrict__ ad = (float4*)(g_buf2 + (size_t)d * HH);
#pragma unroll
    for (int i = 0; i < 2; i++) {
        int c = lane + i * 32;       // 0..63 float4s = 256 floats
        float4 v = hs[c];
        atomicAdd(&ad[c], make_float4(v.x * nrm, v.y * nrm, v.z * nrm, v.w * nrm));
    }
}

// ---------------- self-loop + bias + relu (in place into buf2) -------------
__global__ void k_post(const float* __restrict__ b) {
    int n = blockIdx.x;
    int c = threadIdx.x;
    float di = g_dinv[n];
    size_t idx = (size_t)n * HH + c;
    float v = g_buf2[idx] + g_buf1[idx] * (di * di) + b[c];
    g_buf2[idx] = fmaxf(v, 0.0f);
}

// ---------------- global mean pool -----------------------------------------
__global__ void k_pool(const int* __restrict__ batch) {
    int n = blockIdx.x;
    int c = threadIdx.x;
    int g = batch[n];
    atomicAdd(&g_sums[g * HH + c], g_buf2[(size_t)n * HH + c]);
    if (c == 0) atomicAdd(&g_cnt[g], 1.0f);
}

// ---------------- MLP head: relu(concat(pooled, na) @ W3 + b3) @ W4 + b4 ---
__global__ void k_head(const float* __restrict__ na,
                       const float* __restrict__ W3, const float* __restrict__ b3,
                       const float* __restrict__ W4, const float* __restrict__ b4,
                       float* __restrict__ out) {
    int g = blockIdx.x;
    int j = threadIdx.x;   // 32 threads, one per hidden unit
    __shared__ float zsh[32];

    float inv = 1.0f / fmaxf(g_cnt[g], 1.0f);
    float acc = b3[j];
#pragma unroll 8
    for (int k = 0; k < HH; k++)
        acc += (g_sums[g * HH + k] * inv) * W3[k * 32 + j];
    acc += na[g] * W3[HH * 32 + j];   // num_atoms feature (row 256 of W3)
    zsh[j] = fmaxf(acc, 0.0f);
    __syncthreads();

    if (j < TT) {
        float o = b4[j];
#pragma unroll
        for (int t = 0; t < 32; t++) o += zsh[t] * W4[t * TT + j];
        out[g * TT + j] = o;
    }
}

// ---------------- launch ----------------------------------------------------
extern "C" void kernel_launch(void* const* d_in, const int* in_sizes, int n_in,
                              void* d_out, int out_size) {
    const float* x     = (const float*)d_in[0];
    const int*   ei    = (const int*)  d_in[1];
    const int*   batch = (const int*)  d_in[2];
    const float* na    = (const float*)d_in[3];
    const float* W1    = (const float*)d_in[4];
    const float* b1    = (const float*)d_in[5];
    const float* W2    = (const float*)d_in[6];
    const float* b2    = (const float*)d_in[7];
    const float* W3    = (const float*)d_in[8];
    const float* b3    = (const float*)d_in[9];
    const float* W4    = (const float*)d_in[10];
    const float* b4    = (const float*)d_in[11];
    float* out = (float*)d_out;

    // degree -> dinv (idx 0-2)
    k_init_dinv<<<(NN + 255) / 256, 256>>>();
    k_deg<<<(EE + 255) / 256, 256>>>(ei);
    k_fin_dinv<<<(NN + 255) / 256, 256>>>();

    dim3 gemm_grid(HH / 128, (NN + 127) / 128);

    // idx 3: layer-1 GEMM — ncu profiles this launch
    k_gemm<FF, false><<<gemm_grid, 256>>>(x, W1);

    // Layer 1: zero ; agg ; relu(agg + selfloop + b1)
    k_zero_buf2<<<1024, 256>>>();
    k_agg<<<((size_t)EE * 32 + 255) / 256, 256>>>(ei);
    k_post<<<NN, 256>>>(b1);

    // Layer 2: h = a1 @ W2 ; zero ; agg ; relu(agg + selfloop + b2)
    k_gemm<HH, true><<<gemm_grid, 256>>>(nullptr, W2);
    k_zero_buf2<<<1024, 256>>>();
    k_agg<<<((size_t)EE * 32 + 255) / 256, 256>>>(ei);
    k_post<<<NN, 256>>>(b2);

    // Pool + head
    k_zero_pool<<<(GG * HH + 255) / 256, 256>>>();
    k_pool<<<NN, 256>>>(batch);
    k_head<<<GG, 32>>>(na, W3, b3, W4, b4, out);
}